// round 4
// baseline (speedup 1.0000x reference)
#include <cuda_runtime.h>
#include <math.h>

// Problem geometry (fixed by setup_inputs): B=16, C=3, H=W=512
#define NIMG   48
#define HDIM   512
#define WDIM   512
#define LIMG   (HDIM*WDIM)        // 262144 per image
#define NELEM  (NIMG*LIMG)        // 12,582,912
#define WPI    8192               // 32-bit mask words per image
#define NWORDS (NIMG*WPI)         // 393,216
#define CHUNK  1024
#define CPI    256                // chunks per image
#define NCHUNK (NIMG*CPI)         // 12288
#define LOSS_BLOCKS  (NELEM/2048) // 6144
#define PLOSS_BLOCKS (NELEM/2048) // 6144

// ---- static scratch ----
__device__ float    gP[NELEM];    // compacted x at (t>0), per image, original order
__device__ float    gF[NELEM];    // compacted x at chosen mask, per image
__device__ unsigned gTB[NWORDS];  // packed bits: t > 0
__device__ unsigned gXB[NWORDS];  // packed bits: x > 0
__device__ unsigned gDL[NWORDS];  // 7x7-dilated bits (== aug_pos)
__device__ int gCntPos[NCHUNK], gCntFp[NCHUNK], gCntNeg[NCHUNK];
__device__ int gOffPos[NCHUNK], gOffFp[NCHUNK], gOffNeg[NCHUNK];
__device__ int gRowPos[NIMG],   gRowFp[NIMG],   gRowNeg[NIMG];
__device__ double gAcc;

__device__ __forceinline__ int reflect512(int c) {
    c = (c < 0) ? -c : c;
    return (c > 511) ? (1022 - c) : c;
}

__device__ __forceinline__ float softplusf(float z) {
    return fmaxf(z, 0.f) + __logf(1.f + __expf(-fabsf(z)));
}

__device__ __forceinline__ unsigned mask16_of(const float4 a, const float4 b,
                                              const float4 c, const float4 d) {
    unsigned m = 0;
    m |= (a.x > 0.f) ? 0x0001u : 0u;  m |= (a.y > 0.f) ? 0x0002u : 0u;
    m |= (a.z > 0.f) ? 0x0004u : 0u;  m |= (a.w > 0.f) ? 0x0008u : 0u;
    m |= (b.x > 0.f) ? 0x0010u : 0u;  m |= (b.y > 0.f) ? 0x0020u : 0u;
    m |= (b.z > 0.f) ? 0x0040u : 0u;  m |= (b.w > 0.f) ? 0x0080u : 0u;
    m |= (c.x > 0.f) ? 0x0100u : 0u;  m |= (c.y > 0.f) ? 0x0200u : 0u;
    m |= (c.z > 0.f) ? 0x0400u : 0u;  m |= (c.w > 0.f) ? 0x0800u : 0u;
    m |= (d.x > 0.f) ? 0x1000u : 0u;  m |= (d.y > 0.f) ? 0x2000u : 0u;
    m |= (d.z > 0.f) ? 0x4000u : 0u;  m |= (d.w > 0.f) ? 0x8000u : 0u;
    return m;
}

// ---- K1: bit pack (t>0), (x>0) via float4 loads + lane-pair shfl merge ----
__global__ void k_pack(const float* __restrict__ t, const float* __restrict__ x) {
    if (blockIdx.x == 0 && threadIdx.x == 0) gAcc = 0.0;
    int gtid = blockIdx.x * 256 + threadIdx.x;
    size_t base = (size_t)gtid * 16;
    const float4* tp = (const float4*)(t + base);
    const float4* xp = (const float4*)(x + base);
    float4 t0 = tp[0], t1 = tp[1], t2 = tp[2], t3 = tp[3];
    float4 x0 = xp[0], x1 = xp[1], x2 = xp[2], x3 = xp[3];
    unsigned mt = mask16_of(t0, t1, t2, t3);
    unsigned mx = mask16_of(x0, x1, x2, x3);
    unsigned ot = __shfl_xor_sync(0xFFFFFFFFu, mt, 1);
    unsigned ox = __shfl_xor_sync(0xFFFFFFFFu, mx, 1);
    if (!(gtid & 1)) {
        int w = gtid >> 1;
        gTB[w] = mt | (ot << 16);
        gXB[w] = mx | (ox << 16);
    }
}

// ---- K2: fused 7-wide horizontal + vertical OR-dilation (reflect) ----
__device__ __forceinline__ unsigned hdil(const unsigned* __restrict__ rowTB, int ww) {
    unsigned cur = rowTB[ww];
    unsigned long long ext = ((unsigned long long)cur) << 3;  // bit k <-> col c0-3+k
    if (ww > 0) {
        ext |= (rowTB[ww - 1] >> 29);
    } else {  // reflect: cols -1,-2,-3 -> 1,2,3
        ext |= ((cur >> 3) & 1u) | (((cur >> 2) & 1u) << 1) | (((cur >> 1) & 1u) << 2);
    }
    if (ww < 15) {
        ext |= ((unsigned long long)(rowTB[ww + 1] & 7u)) << 35;
    } else {  // reflect: cols 512,513,514 -> 510,509,508
        ext |= ((unsigned long long)((cur >> 30) & 1u)) << 35
             | ((unsigned long long)((cur >> 29) & 1u)) << 36
             | ((unsigned long long)((cur >> 28) & 1u)) << 37;
    }
    unsigned long long m = ext;
    m |= m >> 1; m |= m >> 2; m |= m >> 3;   // OR over 7-window
    return (unsigned)m;
}

__global__ void k_dil() {
    int w = blockIdx.x * blockDim.x + threadIdx.x;
    int img = w >> 13, rem = w & 8191, h = rem >> 4, ww = rem & 15;
    const unsigned* ib = gTB + (img << 13);
    unsigned d = 0u;
    #pragma unroll
    for (int dh = -3; dh <= 3; dh++) {
        int hh = reflect512(h + dh);
        d |= hdil(ib + (hh << 4), ww);
    }
    gDL[w] = d;
}

// ---- K3: per-image counts + exclusive scan over 256 chunks (1 block/image) ----
__global__ void k_countscan() {
    int img = blockIdx.x, tid = threadIdx.x;
    const unsigned* tb = gTB + (img << 13);
    const unsigned* xb = gXB + (img << 13);
    const unsigned* db = gDL + (img << 13);
    int p = 0, f = 0, n = 0;
    int w0 = tid * 32;                 // thread == chunk (32 words)
    #pragma unroll 8
    for (int k = 0; k < 32; k++) {
        unsigned T = tb[w0 + k], X = xb[w0 + k], D = db[w0 + k];
        p += __popc(T);
        f += __popc(X & ~D);
        n += __popc(~D);
    }
    int cp = p, cf = f, cn = n;        // chunk counts
    int lane = tid & 31, w = tid >> 5;
    #pragma unroll
    for (int o = 1; o < 32; o <<= 1) {
        int ap = __shfl_up_sync(0xFFFFFFFFu, p, o);
        int af = __shfl_up_sync(0xFFFFFFFFu, f, o);
        int an = __shfl_up_sync(0xFFFFFFFFu, n, o);
        if (lane >= o) { p += ap; f += af; n += an; }
    }
    __shared__ int wp[8], wf[8], wn[8];
    if (lane == 31) { wp[w] = p; wf[w] = f; wn[w] = n; }
    __syncthreads();
    int bp = 0, bf = 0, bn = 0;
    for (int k = 0; k < w; k++) { bp += wp[k]; bf += wf[k]; bn += wn[k]; }
    int ip = bp + p, iff = bf + f, in = bn + n;   // inclusive
    int ci = img * CPI + tid;
    int base = img * LIMG;
    gCntPos[ci] = cp; gCntFp[ci] = cf; gCntNeg[ci] = cn;
    gOffPos[ci] = base + ip - cp;
    gOffFp[ci]  = base + iff - cf;
    gOffNeg[ci] = base + in - cn;
    if (tid == 255) { gRowPos[img] = ip; gRowFp[img] = iff; gRowNeg[img] = in; }
}

// ---- K4: ordered compaction, 4 elems/thread, shared staging ----
__global__ void k_write(const float* __restrict__ x) {
    __shared__ float sP[CHUNK];
    __shared__ float sF[CHUNK];
    __shared__ int wtot[8];
    int c   = blockIdx.x;
    int tid = threadIdx.x;
    int img = c >> 8;
    bool useFp = gRowFp[img] > 0;
    int ebase = c * CHUNK + tid * 4;
    unsigned wordT = gTB[(c << 5) + (tid >> 3)];
    unsigned wordD = gDL[(c << 5) + (tid >> 3)];
    int sh = (tid & 7) << 2;
    unsigned tb = (wordT >> sh) & 0xFu;
    unsigned db = (wordD >> sh) & 0xFu;

    float4 v = *(const float4*)(x + ebase);
    float xv[4] = {v.x, v.y, v.z, v.w};
    unsigned sb = 0u;
    #pragma unroll
    for (int i = 0; i < 4; i++) if (xv[i] > 0.f) sb |= 1u << i;
    unsigned cm = (useFp ? (sb & ~db) : ~db) & 0xFu;

    int packed = __popc(tb) | (__popc(cm) << 16);
    int lane = tid & 31, wid = tid >> 5;
    int s = packed;
    #pragma unroll
    for (int o = 1; o < 32; o <<= 1) {
        int nn = __shfl_up_sync(0xFFFFFFFFu, s, o);
        if (lane >= o) s += nn;
    }
    if (lane == 31) wtot[wid] = s;
    __syncthreads();
    int wbase = 0;
    for (int k = 0; k < wid; k++) wbase += wtot[k];
    int excl = wbase + s - packed;

    int pLoc = excl & 0xFFFF;
    int cLoc = excl >> 16;
    #pragma unroll
    for (int i = 0; i < 4; i++) {
        if ((tb >> i) & 1) sP[pLoc++] = xv[i];
        if ((cm >> i) & 1) sF[cLoc++] = xv[i];
    }
    __syncthreads();

    int totP = gCntPos[c];
    int totC = useFp ? gCntFp[c] : gCntNeg[c];
    float* __restrict__ dP = gP + gOffPos[c];
    float* __restrict__ dF = gF + (useFp ? gOffFp[c] : gOffNeg[c]);
    for (int i = tid; i < totP; i += 256) dP[i] = sP[i];
    for (int i = tid; i < totC; i += 256) dF[i] = sF[i];
}

// ---- K5: fused loss. Blocks [0,LOSS_BLOCKS): per-element terms paired with x.
//      Blocks [LOSS_BLOCKS, +PLOSS_BLOCKS): P-only terms folded via cyclic
//      multiplicity m_i = floor(L/cp) + (i < L mod cp). ----
__global__ void k_loss(const float* __restrict__ x) {
    int b = blockIdx.x;
    float acc = 0.f;
    if (b < LOSS_BLOCKS) {
        int img = b >> 7;
        int e0  = (b & 127) * 2048 + threadIdx.x;      // within-image index
        unsigned cp = (unsigned)gRowPos[img];
        unsigned rf = (unsigned)gRowFp[img];
        unsigned rn = (unsigned)gRowNeg[img];
        unsigned cf = rf ? rf : rn;
        const float* __restrict__ Pb = gP + (size_t)img * LIMG;
        const float* __restrict__ Fb = gF + (size_t)img * LIMG;
        const float* __restrict__ xb = x + (size_t)img * LIMG;
        const unsigned* __restrict__ tbw = gTB + ((size_t)img * LIMG >> 5);
        unsigned rP = cp ? ((unsigned)e0 % cp) : 0u;
        unsigned rF = cf ? ((unsigned)e0 % cf) : 0u;
        #pragma unroll
        for (int j = 0; j < 8; j++) {
            int e = e0 + 256 * j;
            float xx = xb[e];
            unsigned tbit = (tbw[e >> 5] >> (e & 31)) & 1u;
            float p = cp ? Pb[rP] : 5.0f;
            float s = p * xx;
            acc += softplusf(s) - (tbit ? s : 0.f);
            if (cf) {
                float f = Fb[rF];
                acc += 0.1f * softplusf(p * f);
                rF += 256u; while (rF >= cf) rF -= cf;
            }
            if (cp) { rP += 256u; while (rP >= cp) rP -= cp; }
        }
    } else {
        int pb  = b - LOSS_BLOCKS;
        int img = pb >> 7;
        int i0  = (pb & 127) * 2048 + threadIdx.x;
        unsigned cp = (unsigned)gRowPos[img];
        unsigned rf = (unsigned)gRowFp[img];
        unsigned rn = (unsigned)gRowNeg[img];
        bool cf0 = (rf == 0u && rn == 0u);             // F is the -5 fallback
        if (cp) {
            unsigned q = (unsigned)LIMG / cp, rr = (unsigned)LIMG - q * cp;
            const float* __restrict__ Pb = gP + (size_t)img * LIMG;
            #pragma unroll
            for (int j = 0; j < 8; j++) {
                unsigned i = (unsigned)i0 + 256u * j;
                if (i < cp) {
                    float pv = Pb[i];
                    float m = (float)(q + (i < rr ? 1u : 0u));
                    float term = softplusf(-pv);                 // bce(dup_pos, 1)
                    if (cf0) term += 0.1f * softplusf(-5.0f * pv);
                    acc += m * term;
                }
            }
        } else if ((pb & 127) == 0 && threadIdx.x == 0) {
            // no positives: p == 5 everywhere
            float t2 = softplusf(-5.f);
            float t3 = cf0 ? 0.1f * softplusf(-25.f) : 0.f;
            acc = (float)LIMG * (t2 + t3);
        }
    }

    int lane = threadIdx.x & 31, wid = threadIdx.x >> 5;
    #pragma unroll
    for (int o = 16; o > 0; o >>= 1) acc += __shfl_down_sync(0xFFFFFFFFu, acc, o);
    __shared__ float ws[8];
    if (lane == 0) ws[wid] = acc;
    __syncthreads();
    if (threadIdx.x == 0) {
        float s = 0.f;
        #pragma unroll
        for (int k = 0; k < 8; k++) s += ws[k];
        atomicAdd(&gAcc, (double)s);
    }
}

// ---- K6: finalize ----
__global__ void k_final(float* __restrict__ out) {
    out[0] = (float)(gAcc / (double)NELEM);
}

extern "C" void kernel_launch(void* const* d_in, const int* in_sizes, int n_in,
                              void* d_out, int out_size) {
    const float* x = (const float*)d_in[0];   // input
    const float* t = (const float*)d_in[1];   // target
    float* out = (float*)d_out;
    (void)in_sizes; (void)n_in; (void)out_size;

    k_pack     <<<NELEM / 4096, 256>>>(t, x);
    k_dil      <<<NWORDS / 256, 256>>>();
    k_countscan<<<NIMG, 256>>>();
    k_write    <<<NCHUNK, 256>>>(x);
    k_loss     <<<LOSS_BLOCKS + PLOSS_BLOCKS, 256>>>(x);
    k_final    <<<1, 1>>>(out);
}

// round 5
// speedup vs baseline: 1.0714x; 1.0714x over previous
#include <cuda_runtime.h>
#include <math.h>

// Problem geometry (fixed by setup_inputs): B=16, C=3, H=W=512
#define NIMG   48
#define HDIM   512
#define WDIM   512
#define LIMG   (HDIM*WDIM)        // 262144 per image
#define NELEM  (NIMG*LIMG)        // 12,582,912
#define WPI    8192               // 32-bit mask words per image
#define NWORDS (NIMG*WPI)         // 393,216
#define WCPI   2048               // 128-element warp-chunks per image
#define NWC    (NIMG*WCPI)        // 98304
#define LOSS_BLOCKS  (NELEM/2048) // 6144
#define PLOSS_BLOCKS (NELEM/2048) // 6144

// ---- static scratch ----
__device__ float    gP[NELEM];    // compacted x at (t>0), per image, original order
__device__ float    gF[NELEM];    // compacted x at chosen mask, per image
__device__ unsigned gTB[NWORDS];  // packed bits: t > 0
__device__ unsigned gXB[NWORDS];  // packed bits: x > 0
__device__ unsigned gDL[NWORDS];  // 7x7-dilated bits (== aug_pos)
__device__ int gWOffPos[NWC], gWOffFp[NWC], gWOffNeg[NWC];
__device__ int gRowPos[NIMG], gRowFp[NIMG], gRowNeg[NIMG];
__device__ double gAcc;

__device__ __forceinline__ int reflect512(int c) {
    c = (c < 0) ? -c : c;
    return (c > 511) ? (1022 - c) : c;
}

__device__ __forceinline__ float softplusf(float z) {
    return fmaxf(z, 0.f) + __logf(1.f + __expf(-fabsf(z)));
}

__device__ __forceinline__ unsigned mask16_of(const float4 a, const float4 b,
                                              const float4 c, const float4 d) {
    unsigned m = 0;
    m |= (a.x > 0.f) ? 0x0001u : 0u;  m |= (a.y > 0.f) ? 0x0002u : 0u;
    m |= (a.z > 0.f) ? 0x0004u : 0u;  m |= (a.w > 0.f) ? 0x0008u : 0u;
    m |= (b.x > 0.f) ? 0x0010u : 0u;  m |= (b.y > 0.f) ? 0x0020u : 0u;
    m |= (b.z > 0.f) ? 0x0040u : 0u;  m |= (b.w > 0.f) ? 0x0080u : 0u;
    m |= (c.x > 0.f) ? 0x0100u : 0u;  m |= (c.y > 0.f) ? 0x0200u : 0u;
    m |= (c.z > 0.f) ? 0x0400u : 0u;  m |= (c.w > 0.f) ? 0x0800u : 0u;
    m |= (d.x > 0.f) ? 0x1000u : 0u;  m |= (d.y > 0.f) ? 0x2000u : 0u;
    m |= (d.z > 0.f) ? 0x4000u : 0u;  m |= (d.w > 0.f) ? 0x8000u : 0u;
    return m;
}

// ---- K1: bit pack (t>0), (x>0) via float4 loads + lane-pair shfl merge ----
__global__ void k_pack(const float* __restrict__ t, const float* __restrict__ x) {
    if (blockIdx.x == 0 && threadIdx.x == 0) gAcc = 0.0;
    int gtid = blockIdx.x * 256 + threadIdx.x;
    size_t base = (size_t)gtid * 16;
    const float4* tp = (const float4*)(t + base);
    const float4* xp = (const float4*)(x + base);
    float4 t0 = tp[0], t1 = tp[1], t2 = tp[2], t3 = tp[3];
    float4 x0 = xp[0], x1 = xp[1], x2 = xp[2], x3 = xp[3];
    unsigned mt = mask16_of(t0, t1, t2, t3);
    unsigned mx = mask16_of(x0, x1, x2, x3);
    unsigned ot = __shfl_xor_sync(0xFFFFFFFFu, mt, 1);
    unsigned ox = __shfl_xor_sync(0xFFFFFFFFu, mx, 1);
    if (!(gtid & 1)) {
        int w = gtid >> 1;
        gTB[w] = mt | (ot << 16);
        gXB[w] = mx | (ox << 16);
    }
}

// ---- K2: fused 7-wide horizontal + vertical OR-dilation (reflect) ----
__device__ __forceinline__ unsigned hdil(const unsigned* __restrict__ rowTB, int ww) {
    unsigned cur = rowTB[ww];
    unsigned long long ext = ((unsigned long long)cur) << 3;  // bit k <-> col c0-3+k
    if (ww > 0) {
        ext |= (rowTB[ww - 1] >> 29);
    } else {  // reflect: cols -1,-2,-3 -> 1,2,3
        ext |= ((cur >> 3) & 1u) | (((cur >> 2) & 1u) << 1) | (((cur >> 1) & 1u) << 2);
    }
    if (ww < 15) {
        ext |= ((unsigned long long)(rowTB[ww + 1] & 7u)) << 35;
    } else {  // reflect: cols 512,513,514 -> 510,509,508
        ext |= ((unsigned long long)((cur >> 30) & 1u)) << 35
             | ((unsigned long long)((cur >> 29) & 1u)) << 36
             | ((unsigned long long)((cur >> 28) & 1u)) << 37;
    }
    unsigned long long m = ext;
    m |= m >> 1; m |= m >> 2; m |= m >> 3;   // OR over 7-window
    return (unsigned)m;
}

__global__ void k_dil() {
    int w = blockIdx.x * blockDim.x + threadIdx.x;
    int img = w >> 13, rem = w & 8191, h = rem >> 4, ww = rem & 15;
    const unsigned* ib = gTB + (img << 13);
    unsigned d = 0u;
    #pragma unroll
    for (int dh = -3; dh <= 3; dh++) {
        int hh = reflect512(h + dh);
        d |= hdil(ib + (hh << 4), ww);
    }
    gDL[w] = d;
}

// ---- K3: per-image counts + scan -> per-warpchunk (128-elem) offsets ----
__global__ void k_countscan() {
    int img = blockIdx.x, tid = threadIdx.x;
    const unsigned* tb = gTB + (img << 13);
    const unsigned* xb = gXB + (img << 13);
    const unsigned* db = gDL + (img << 13);
    int w0 = tid * 32;                 // 8 warpchunks (32 words) per thread
    int lp[8], lf[8], ln[8];
    int p = 0, f = 0, n = 0;
    #pragma unroll
    for (int j = 0; j < 8; j++) {
        int pj = 0, fj = 0, nj = 0;
        #pragma unroll
        for (int k = 0; k < 4; k++) {
            unsigned T = tb[w0 + j * 4 + k], X = xb[w0 + j * 4 + k], D = db[w0 + j * 4 + k];
            pj += __popc(T);
            fj += __popc(X & ~D);
            nj += __popc(~D);
        }
        lp[j] = p; lf[j] = f; ln[j] = n;   // thread-local exclusive
        p += pj; f += fj; n += nj;
    }
    int lane = tid & 31, w = tid >> 5;
    int ip = p, iff = f, in = n;
    #pragma unroll
    for (int o = 1; o < 32; o <<= 1) {
        int ap = __shfl_up_sync(0xFFFFFFFFu, ip, o);
        int af = __shfl_up_sync(0xFFFFFFFFu, iff, o);
        int an = __shfl_up_sync(0xFFFFFFFFu, in, o);
        if (lane >= o) { ip += ap; iff += af; in += an; }
    }
    __shared__ int wp[8], wf[8], wn[8];
    if (lane == 31) { wp[w] = ip; wf[w] = iff; wn[w] = in; }
    __syncthreads();
    int bp = 0, bf = 0, bn = 0;
    for (int k = 0; k < w; k++) { bp += wp[k]; bf += wf[k]; bn += wn[k]; }
    int ep = bp + ip - p, ef = bf + iff - f, en = bn + in - n;  // thread exclusive
    int base = img * LIMG;
    int wc0 = img * WCPI + tid * 8;
    #pragma unroll
    for (int j = 0; j < 8; j++) {
        gWOffPos[wc0 + j] = base + ep + lp[j];
        gWOffFp[wc0 + j]  = base + ef + lf[j];
        gWOffNeg[wc0 + j] = base + en + ln[j];
    }
    if (tid == 255) { gRowPos[img] = bp + ip; gRowFp[img] = bf + iff; gRowNeg[img] = bn + in; }
}

// ---- K4: warp-autonomous ordered compaction (no smem, no block sync) ----
__global__ void k_write(const float* __restrict__ x) {
    int wc   = (blockIdx.x * blockDim.x + threadIdx.x) >> 5;  // global warpchunk
    int lane = threadIdx.x & 31;
    int img  = wc >> 11;
    bool useFp = gRowFp[img] > 0;
    int ebase = wc * 128 + lane * 4;
    unsigned wordT = gTB[(wc << 2) + (lane >> 3)];
    unsigned wordD = gDL[(wc << 2) + (lane >> 3)];
    int sh = (lane & 7) << 2;
    unsigned tb = (wordT >> sh) & 0xFu;
    unsigned db = (wordD >> sh) & 0xFu;

    float4 v = *(const float4*)(x + ebase);
    float xv[4] = {v.x, v.y, v.z, v.w};
    unsigned sb = 0u;
    #pragma unroll
    for (int i = 0; i < 4; i++) if (xv[i] > 0.f) sb |= 1u << i;
    unsigned cm = (useFp ? (sb & ~db) : ~db) & 0xFu;

    int packed = __popc(tb) | (__popc(cm) << 16);
    int s = packed;
    #pragma unroll
    for (int o = 1; o < 32; o <<= 1) {
        int nn = __shfl_up_sync(0xFFFFFFFFu, s, o);
        if (lane >= o) s += nn;
    }
    int excl = s - packed;
    int pOff = gWOffPos[wc] + (excl & 0xFFFF);
    int cOff = (useFp ? gWOffFp[wc] : gWOffNeg[wc]) + (excl >> 16);
    #pragma unroll
    for (int i = 0; i < 4; i++) {
        if ((tb >> i) & 1) gP[pOff++] = xv[i];
        if ((cm >> i) & 1) gF[cOff++] = xv[i];
    }
}

// ---- K5: fused loss. Blocks [0,LOSS_BLOCKS): per-element terms paired with x.
//      Blocks [LOSS_BLOCKS, +PLOSS_BLOCKS): P-only terms folded via cyclic
//      multiplicity m_i = floor(L/cp) + (i < L mod cp). ----
__global__ void k_loss(const float* __restrict__ x) {
    int b = blockIdx.x;
    float acc = 0.f;
    if (b < LOSS_BLOCKS) {
        int img = b >> 7;
        int e0  = (b & 127) * 2048 + threadIdx.x;      // within-image index
        unsigned cp = (unsigned)gRowPos[img];
        unsigned rf = (unsigned)gRowFp[img];
        unsigned rn = (unsigned)gRowNeg[img];
        unsigned cf = rf ? rf : rn;
        const float* __restrict__ Pb = gP + (size_t)img * LIMG;
        const float* __restrict__ Fb = gF + (size_t)img * LIMG;
        const float* __restrict__ xb = x + (size_t)img * LIMG;
        const unsigned* __restrict__ tbw = gTB + ((size_t)img * LIMG >> 5);
        unsigned rP = cp ? ((unsigned)e0 % cp) : 0u;
        unsigned rF = cf ? ((unsigned)e0 % cf) : 0u;
        #pragma unroll
        for (int j = 0; j < 8; j++) {
            int e = e0 + 256 * j;
            float xx = xb[e];
            unsigned tbit = (tbw[e >> 5] >> (e & 31)) & 1u;
            float p = cp ? Pb[rP] : 5.0f;
            float s = p * xx;
            acc += softplusf(s) - (tbit ? s : 0.f);
            if (cf) {
                float f = Fb[rF];
                acc += 0.1f * softplusf(p * f);
                rF += 256u; while (rF >= cf) rF -= cf;
            }
            if (cp) { rP += 256u; while (rP >= cp) rP -= cp; }
        }
    } else {
        int pb  = b - LOSS_BLOCKS;
        int img = pb >> 7;
        int i0  = (pb & 127) * 2048 + threadIdx.x;
        unsigned cp = (unsigned)gRowPos[img];
        unsigned rf = (unsigned)gRowFp[img];
        unsigned rn = (unsigned)gRowNeg[img];
        bool cf0 = (rf == 0u && rn == 0u);             // F is the -5 fallback
        if (cp) {
            unsigned q = (unsigned)LIMG / cp, rr = (unsigned)LIMG - q * cp;
            const float* __restrict__ Pb = gP + (size_t)img * LIMG;
            #pragma unroll
            for (int j = 0; j < 8; j++) {
                unsigned i = (unsigned)i0 + 256u * j;
                if (i < cp) {
                    float pv = Pb[i];
                    float m = (float)(q + (i < rr ? 1u : 0u));
                    float term = softplusf(-pv);                 // bce(dup_pos, 1)
                    if (cf0) term += 0.1f * softplusf(-5.0f * pv);
                    acc += m * term;
                }
            }
        } else if ((pb & 127) == 0 && threadIdx.x == 0) {
            // no positives: p == 5 everywhere
            float t2 = softplusf(-5.f);
            float t3 = cf0 ? 0.1f * softplusf(-25.f) : 0.f;
            acc = (float)LIMG * (t2 + t3);
        }
    }

    int lane = threadIdx.x & 31, wid = threadIdx.x >> 5;
    #pragma unroll
    for (int o = 16; o > 0; o >>= 1) acc += __shfl_down_sync(0xFFFFFFFFu, acc, o);
    __shared__ float ws[8];
    if (lane == 0) ws[wid] = acc;
    __syncthreads();
    if (threadIdx.x == 0) {
        float s = 0.f;
        #pragma unroll
        for (int k = 0; k < 8; k++) s += ws[k];
        atomicAdd(&gAcc, (double)s);
    }
}

// ---- K6: finalize ----
__global__ void k_final(float* __restrict__ out) {
    out[0] = (float)(gAcc / (double)NELEM);
}

extern "C" void kernel_launch(void* const* d_in, const int* in_sizes, int n_in,
                              void* d_out, int out_size) {
    const float* x = (const float*)d_in[0];   // input
    const float* t = (const float*)d_in[1];   // target
    float* out = (float*)d_out;
    (void)in_sizes; (void)n_in; (void)out_size;

    k_pack     <<<NELEM / 4096, 256>>>(t, x);
    k_dil      <<<NWORDS / 256, 256>>>();
    k_countscan<<<NIMG, 256>>>();
    k_write    <<<(NWC * 32) / 512, 512>>>(x);
    k_loss     <<<LOSS_BLOCKS + PLOSS_BLOCKS, 256>>>(x);
    k_final    <<<1, 1>>>(out);
}